// round 16
// baseline (speedup 1.0000x reference)
#include <cuda_runtime.h>
#include <cuda_bf16.h>
#include <math.h>
#include <stdint.h>

#define N_NODES 100000
#define N_EDGES 1600000
#define D 64
#define EPSV 1e-7f
#define SCAN_BLK 1024
#define N_SCAN_BLKS ((N_NODES + SCAN_BLK - 1) / SCAN_BLK)   // 98

// ---- mma finalize geometry ----
#define TM 32                       // nodes per CTA tile
#define KSTEPS 28                   // 448 / 16
#define YSTRIDE 456                 // bf16 per Y row (448 + 8 pad)
#define YBYTES (TM * YSTRIDE * 2)   // 29184 B per array
#define CRED_OFF (2 * YBYTES)       // C-reduce buffer after Yh+Yl (58368)
#define CRED_BYTES (8 * 32 * 16 * 4) // 8 partial warps x 32 lanes x 16 f32
#define FIN_SMEM (CRED_OFF + CRED_BYTES)   // 74752 B -> 2 CTAs/SM
#define FIN_THREADS 384

// Scratch (device globals; allocation is forbidden)
__device__ int   g_cnt[N_NODES];
__device__ int   g_rowptr[N_NODES + 1];
__device__ int   g_rank[N_EDGES];
__device__ int   g_bsum[N_SCAN_BLKS];
__device__ int   g_csr[N_EDGES];
// fragment-packed weights: [kstep s][nfrag fg][lane] -> u64 (b0 | b1<<32)
__device__ unsigned long long g_wfh[KSTEPS * 8 * 32];
__device__ unsigned long long g_wfl[KSTEPS * 8 * 32];

__device__ __forceinline__ unsigned short bf2us(__nv_bfloat16 h) {
    return *reinterpret_cast<unsigned short*>(&h);
}
__device__ __forceinline__ void bf16_split(float v, __nv_bfloat16& h,
                                           __nv_bfloat16& l) {
    h = __float2bfloat16_rn(v);
    l = __float2bfloat16_rn(v - __bfloat162float(h));
}

// ---------------------------------------------------------------------------
// K0: pack weights into mma fragment layout (hi/lo) + zero g_cnt.
// ---------------------------------------------------------------------------
__device__ __forceinline__ float wcat(const float* __restrict__ pre_w,
                                      const float* __restrict__ lin_w,
                                      int o, int k) {
    int seg = k >> 6;
    int ki = k & 63;
    return (seg < 6) ? __ldg(pre_w + (seg * 64 + o) * 64 + ki)
                     : __ldg(lin_w + o * 64 + ki);
}

__global__ void permute_zero_kernel(const float* __restrict__ pre_w,
                                    const float* __restrict__ lin_w, int N) {
    int idx = blockIdx.x * blockDim.x + threadIdx.x;
    if (idx < KSTEPS * 8 * 32) {
        int lane = idx & 31;
        int fg = (idx >> 5) & 7;
        int s = idx >> 8;
        int g = lane >> 2, tg = lane & 3;
        int o = fg * 8 + g;
        int k0 = s * 16 + tg * 2;
        float v0 = wcat(pre_w, lin_w, o, k0);
        float v1 = wcat(pre_w, lin_w, o, k0 + 1);
        float v8 = wcat(pre_w, lin_w, o, k0 + 8);
        float v9 = wcat(pre_w, lin_w, o, k0 + 9);
        __nv_bfloat16 h, l;
        uint32_t bh0, bh1, bl0, bl1;
        bf16_split(v0, h, l); bh0 = bf2us(h);        bl0 = bf2us(l);
        bf16_split(v1, h, l); bh0 |= (uint32_t)bf2us(h) << 16;
                              bl0 |= (uint32_t)bf2us(l) << 16;
        bf16_split(v8, h, l); bh1 = bf2us(h);        bl1 = bf2us(l);
        bf16_split(v9, h, l); bh1 |= (uint32_t)bf2us(h) << 16;
                              bl1 |= (uint32_t)bf2us(l) << 16;
        g_wfh[idx] = (unsigned long long)bh0 | ((unsigned long long)bh1 << 32);
        g_wfl[idx] = (unsigned long long)bl0 | ((unsigned long long)bl1 << 32);
    }
    if (idx < N) g_cnt[idx] = 0;
}

// ---------------------------------------------------------------------------
// K1: histogram + per-edge rank (the only atomic pass)
// ---------------------------------------------------------------------------
__global__ void count_rank_kernel(const int* __restrict__ erow, int E) {
    int e = blockIdx.x * blockDim.x + threadIdx.x;
    if (e < E) g_rank[e] = atomicAdd(&g_cnt[erow[e]], 1);
}

// ---------------------------------------------------------------------------
// K2a/b/c: device-wide exclusive scan
// ---------------------------------------------------------------------------
__global__ void scan_block_kernel(int n) {
    __shared__ int warp_sums[32];
    int i = blockIdx.x * SCAN_BLK + threadIdx.x;
    int v = (i < n) ? g_cnt[i] : 0;
    int lane = threadIdx.x & 31;
    int wid = threadIdx.x >> 5;

    int s = v;
    #pragma unroll
    for (int o = 1; o < 32; o <<= 1) {
        int t = __shfl_up_sync(0xffffffffu, s, o);
        if (lane >= o) s += t;
    }
    if (lane == 31) warp_sums[wid] = s;
    __syncthreads();
    if (wid == 0) {
        int ws = warp_sums[lane];
        #pragma unroll
        for (int o = 1; o < 32; o <<= 1) {
            int t = __shfl_up_sync(0xffffffffu, ws, o);
            if (lane >= o) ws += t;
        }
        warp_sums[lane] = ws;
    }
    __syncthreads();
    int warp_off = (wid == 0) ? 0 : warp_sums[wid - 1];
    if (i < n) g_rowptr[i] = warp_off + s - v;
    if (threadIdx.x == SCAN_BLK - 1) g_bsum[blockIdx.x] = warp_off + s;
}

__global__ void scan_top_kernel(int nb) {
    __shared__ int sh[128];
    int t = threadIdx.x;
    int v = (t < nb) ? g_bsum[t] : 0;
    int lane = t & 31, wid = t >> 5;
    int s = v;
    #pragma unroll
    for (int o = 1; o < 32; o <<= 1) {
        int u = __shfl_up_sync(0xffffffffu, s, o);
        if (lane >= o) s += u;
    }
    if (lane == 31) sh[wid] = s;
    __syncthreads();
    if (t == 0) {
        int acc = 0;
        #pragma unroll
        for (int w = 0; w < 4; ++w) { int x = sh[w]; sh[w] = acc; acc += x; }
    }
    __syncthreads();
    if (t < nb) g_bsum[t] = sh[wid] + s - v;
}

__global__ void scan_add_kernel(int n, int E) {
    int i = blockIdx.x * blockDim.x + threadIdx.x;
    if (i < n) g_rowptr[i] += g_bsum[i >> 10];
    if (i == n) g_rowptr[n] = E;
}

// ---------------------------------------------------------------------------
// K3: atomic-free scatter using precomputed ranks
// ---------------------------------------------------------------------------
__global__ void scatter_kernel(const int* __restrict__ erow,
                               const int* __restrict__ ecol, int E) {
    int e = blockIdx.x * blockDim.x + threadIdx.x;
    if (e < E) {
        int d = erow[e];
        int pos = __ldg(&g_rowptr[d]) + g_rank[e];
        g_csr[pos] = ecol[e];
    }
}

// ---------------------------------------------------------------------------
// K4: fused gather + mma finalize. TM=32, 384 threads, 2 CTAs/SM.
// MMA: 12 warps = 4 slots (node-group x out-half[32]) x 3 pass-warps.
// Each warp runs ONE hi/lo pass over 4 out-fragments (full 64-out coverage);
// partial C reduced via smem.
// ---------------------------------------------------------------------------
__device__ __forceinline__ void mma16816(float& c0, float& c1, float& c2,
                                         float& c3, uint32_t a0, uint32_t a1,
                                         uint32_t a2, uint32_t a3,
                                         uint32_t b0, uint32_t b1) {
    asm volatile(
        "mma.sync.aligned.m16n8k16.row.col.f32.bf16.bf16.f32 "
        "{%0,%1,%2,%3},{%4,%5,%6,%7},{%8,%9},{%0,%1,%2,%3};"
        : "+f"(c0), "+f"(c1), "+f"(c2), "+f"(c3)
        : "r"(a0), "r"(a1), "r"(a2), "r"(a3), "r"(b0), "r"(b1));
}

__device__ __forceinline__ unsigned long long pack4bf(
    float v0, float v1, float v2, float v3, bool lo) {
    __nv_bfloat16 h, l;
    uint32_t w0, w1;
    bf16_split(v0, h, l); w0 = lo ? bf2us(l) : bf2us(h);
    bf16_split(v1, h, l); w0 |= (uint32_t)(lo ? bf2us(l) : bf2us(h)) << 16;
    bf16_split(v2, h, l); w1 = lo ? bf2us(l) : bf2us(h);
    bf16_split(v3, h, l); w1 |= (uint32_t)(lo ? bf2us(l) : bf2us(h)) << 16;
    return (unsigned long long)w0 | ((unsigned long long)w1 << 32);
}

__global__ void __launch_bounds__(FIN_THREADS, 2)
finalize_fused_kernel(const float* __restrict__ x,
                      const float* __restrict__ bias,
                      const float* __restrict__ avg_ptr,
                      float* __restrict__ out,
                      int N) {
    extern __shared__ __nv_bfloat16 Ybuf[];        // Yh, Yl, then Cred (f32)
    __nv_bfloat16* Yh = Ybuf;
    __nv_bfloat16* Yl = Ybuf + TM * YSTRIDE;
    float* Cred = reinterpret_cast<float*>(
        reinterpret_cast<char*>(Ybuf) + CRED_OFF);
    __shared__ float f1s[TM], f2s[TM];

    const int tid = threadIdx.x;
    const int node0 = blockIdx.x * TM;

    // ---- phase 0: per-node degree factors ----
    if (tid < TM) {
        int n = node0 + tid;
        float f1 = 0.f, f2 = 0.f;
        if (n < N) {
            float avg = __ldg(avg_ptr);
            float degf = (float)(__ldg(&g_rowptr[n + 1]) - __ldg(&g_rowptr[n]));
            float logd = __logf(degf + 1.0f);
            f1 = logd * __frcp_rn(avg);
            f2 = avg * __frcp_rn(logd + EPSV);
        }
        f1s[tid] = f1;
        f2s[tid] = f2;
    }
    __syncthreads();

    // ---- phase 1: gather + stage Y hi/lo (16 lanes/node) ----
    {
        const float4* x4 = reinterpret_cast<const float4*>(x);
        for (int p = tid; p < TM * 16; p += FIN_THREADS) {
            int nl = p >> 4;
            int lane16 = p & 15;
            int n = node0 + nl;
            float4 a = make_float4(0.f, 0.f, 0.f, 0.f);
            float4 b = make_float4(0.f, 0.f, 0.f, 0.f);
            float4 xv = make_float4(0.f, 0.f, 0.f, 0.f);
            if (n < N) {
                int beg = __ldg(&g_rowptr[n]);
                int end = __ldg(&g_rowptr[n + 1]);
                int j = beg;
                for (; j + 1 < end; j += 2) {
                    int s0 = __ldg(&g_csr[j]);
                    int s1 = __ldg(&g_csr[j + 1]);
                    float4 v0 = __ldg(&x4[(size_t)s0 * 16 + lane16]);
                    float4 v1 = __ldg(&x4[(size_t)s1 * 16 + lane16]);
                    a.x += v0.x; a.y += v0.y; a.z += v0.z; a.w += v0.w;
                    b.x += v0.x * v0.x; b.y += v0.y * v0.y;
                    b.z += v0.z * v0.z; b.w += v0.w * v0.w;
                    a.x += v1.x; a.y += v1.y; a.z += v1.z; a.w += v1.w;
                    b.x += v1.x * v1.x; b.y += v1.y * v1.y;
                    b.z += v1.z * v1.z; b.w += v1.w * v1.w;
                }
                if (j < end) {
                    int s0 = __ldg(&g_csr[j]);
                    float4 v0 = __ldg(&x4[(size_t)s0 * 16 + lane16]);
                    a.x += v0.x; a.y += v0.y; a.z += v0.z; a.w += v0.w;
                    b.x += v0.x * v0.x; b.y += v0.y * v0.y;
                    b.z += v0.z * v0.z; b.w += v0.w * v0.w;
                }
                xv = __ldg(&x4[(size_t)n * 16 + lane16]);
            }
            float sx = fmaxf(b.x - a.x * a.x, 0.f) + EPSV;
            float sy = fmaxf(b.y - a.y * a.y, 0.f) + EPSV;
            float sz = fmaxf(b.z - a.z * a.z, 0.f) + EPSV;
            float sw = fmaxf(b.w - a.w * a.w, 0.f) + EPSV;
            float4 sd = make_float4(sx * rsqrtf(sx), sy * rsqrtf(sy),
                                    sz * rsqrtf(sz), sw * rsqrtf(sw));
            float f1 = f1s[nl], f2 = f2s[nl];

            unsigned long long* Yh64 = reinterpret_cast<unsigned long long*>(
                Yh + nl * YSTRIDE) + lane16;
            unsigned long long* Yl64 = reinterpret_cast<unsigned long long*>(
                Yl + nl * YSTRIDE) + lane16;

            float4 segv[7];
            segv[0] = a;
            segv[1] = make_float4(f1 * a.x, f1 * a.y, f1 * a.z, f1 * a.w);
            segv[2] = make_float4(f2 * a.x, f2 * a.y, f2 * a.z, f2 * a.w);
            segv[3] = sd;
            segv[4] = make_float4(f1 * sd.x, f1 * sd.y, f1 * sd.z, f1 * sd.w);
            segv[5] = make_float4(f2 * sd.x, f2 * sd.y, f2 * sd.z, f2 * sd.w);
            segv[6] = xv;
            #pragma unroll
            for (int sg = 0; sg < 7; ++sg) {
                Yh64[sg * 16] = pack4bf(segv[sg].x, segv[sg].y,
                                        segv[sg].z, segv[sg].w, false);
                Yl64[sg * 16] = pack4bf(segv[sg].x, segv[sg].y,
                                        segv[sg].z, segv[sg].w, true);
            }
        }
    }
    __syncthreads();

    // ---- phase 2: MMA. 12 warps = 4 slots x 3 passes; 4 frags/warp ----
    const int wid = tid >> 5;
    const int lane = tid & 31;
    const int slot = wid & 3;          // nh2 = slot&1, oh = slot>>1 (32 outs)
    const int pass = wid >> 2;         // 0: Yh*Wh, 1: Yh*Wl, 2: Yl*Wh
    const int nh2 = slot & 1;
    const int oh = slot >> 1;
    const int g = lane >> 2;
    const int tg = lane & 3;

    float acc[4][4];
    #pragma unroll
    for (int fi = 0; fi < 4; ++fi)
        #pragma unroll
        for (int q = 0; q < 4; ++q) acc[fi][q] = 0.f;

    {
        const int r0 = (nh2 * 16 + g) * YSTRIDE;
        const __nv_bfloat16* Ya = (pass < 2) ? Yh : Yl;
        const unsigned long long* Wb = (pass == 1) ? g_wfl : g_wfh;
        #pragma unroll 4
        for (int s = 0; s < KSTEPS; ++s) {
            int kk = s * 16 + tg * 2;
            uint32_t a0 = *(const uint32_t*)(Ya + r0 + kk);
            uint32_t a1 = *(const uint32_t*)(Ya + r0 + 8 * YSTRIDE + kk);
            uint32_t a2 = *(const uint32_t*)(Ya + r0 + kk + 8);
            uint32_t a3 = *(const uint32_t*)(Ya + r0 + 8 * YSTRIDE + kk + 8);
            #pragma unroll
            for (int fi = 0; fi < 4; ++fi) {
                int fg = oh * 4 + fi;
                unsigned long long bv = __ldg(&Wb[(s * 8 + fg) * 32 + lane]);
                mma16816(acc[fi][0], acc[fi][1], acc[fi][2], acc[fi][3],
                         a0, a1, a2, a3,
                         (uint32_t)bv, (uint32_t)(bv >> 32));
            }
        }
    }

    // ---- phase 3: pass reduction via smem ----
    if (pass != 0) {
        float* cb = Cred + ((size_t)((slot * 2 + pass - 1) * 32 + lane)) * 16;
        #pragma unroll
        for (int fi = 0; fi < 4; ++fi)
            *reinterpret_cast<float4*>(cb + fi * 4) =
                make_float4(acc[fi][0], acc[fi][1], acc[fi][2], acc[fi][3]);
    }
    __syncthreads();

    if (pass == 0) {
        #pragma unroll
        for (int pw = 0; pw < 2; ++pw) {
            const float* cb =
                Cred + ((size_t)((slot * 2 + pw) * 32 + lane)) * 16;
            #pragma unroll
            for (int fi = 0; fi < 4; ++fi) {
                float4 pv = *reinterpret_cast<const float4*>(cb + fi * 4);
                acc[fi][0] += pv.x; acc[fi][1] += pv.y;
                acc[fi][2] += pv.z; acc[fi][3] += pv.w;
            }
        }

        // ---- epilogue ----
        #pragma unroll
        for (int fi = 0; fi < 4; ++fi) {
            int o = oh * 32 + fi * 8 + tg * 2;
            float b0 = __ldg(bias + o);
            float b1 = __ldg(bias + o + 1);
            int n0 = node0 + nh2 * 16 + g;
            int n1 = n0 + 8;
            if (n0 < N) {
                *reinterpret_cast<float2*>(out + (size_t)n0 * D + o) =
                    make_float2(acc[fi][0] + b0, acc[fi][1] + b1);
            }
            if (n1 < N) {
                *reinterpret_cast<float2*>(out + (size_t)n1 * D + o) =
                    make_float2(acc[fi][2] + b0, acc[fi][3] + b1);
            }
        }
    }
}

// ---------------------------------------------------------------------------
// Launch. Inputs: x, edge_row, edge_col, pre_w, lin_w, bias, avg_deg_log
// ---------------------------------------------------------------------------
extern "C" void kernel_launch(void* const* d_in, const int* in_sizes, int n_in,
                              void* d_out, int out_size) {
    const float* x       = (const float*)d_in[0];
    const int*   erow    = (const int*)d_in[1];
    const int*   ecol    = (const int*)d_in[2];
    const float* pre_w   = (const float*)d_in[3];
    const float* lin_w   = (const float*)d_in[4];
    const float* bias    = (const float*)d_in[5];
    const float* avg_log = (const float*)d_in[6];

    const int N = in_sizes[0] / D;
    const int E = in_sizes[1];
    float* out = (float*)d_out;

    permute_zero_kernel<<<(N + 255) / 256, 256>>>(pre_w, lin_w, N);
    count_rank_kernel<<<(E + 255) / 256, 256>>>(erow, E);
    int nsb = (N + SCAN_BLK - 1) / SCAN_BLK;
    scan_block_kernel<<<nsb, SCAN_BLK>>>(N);
    scan_top_kernel<<<1, 128>>>(nsb);
    scan_add_kernel<<<(N + 256) / 256, 256>>>(N, E);
    scatter_kernel<<<(E + 255) / 256, 256>>>(erow, ecol, E);

    {
        cudaFuncSetAttribute(finalize_fused_kernel,
                             cudaFuncAttributeMaxDynamicSharedMemorySize,
                             FIN_SMEM);
        int blocks = (N + TM - 1) / TM;
        finalize_fused_kernel<<<blocks, FIN_THREADS, FIN_SMEM>>>(
            x, bias, avg_log, out, N);
    }
}

// round 17
// speedup vs baseline: 1.2230x; 1.2230x over previous
#include <cuda_runtime.h>
#include <cuda_bf16.h>
#include <math.h>
#include <stdint.h>

#define N_NODES 100000
#define N_EDGES 1600000
#define D 64
#define EPSV 1e-7f
#define SCAN_BLK 1024
#define N_SCAN_BLKS ((N_NODES + SCAN_BLK - 1) / SCAN_BLK)   // 98

// ---- mma finalize geometry ----
#define TM 32                       // nodes per CTA tile
#define KSTEPS 28                   // 448 / 16
#define YSTRIDE 456                 // bf16 per Y row (448 + 8 pad)
#define YBYTES (TM * YSTRIDE * 2)   // 29184 B per array
#define FIN_SMEM (2 * YBYTES)       // Yh + Yl = 58368 B -> 3 CTAs/SM

// Scratch (device globals; allocation is forbidden)
__device__ int   g_cnt[N_NODES];
__device__ int   g_rowptr[N_NODES + 1];
__device__ int   g_rank[N_EDGES];
__device__ int   g_bsum[N_SCAN_BLKS];
__device__ int   g_csr[N_EDGES];
// fragment-packed weights: [kstep s][nfrag fg][lane] -> u64 (b0 | b1<<32)
__device__ unsigned long long g_wfh[KSTEPS * 8 * 32];
__device__ unsigned long long g_wfl[KSTEPS * 8 * 32];

__device__ __forceinline__ unsigned short bf2us(__nv_bfloat16 h) {
    return *reinterpret_cast<unsigned short*>(&h);
}
__device__ __forceinline__ void bf16_split(float v, __nv_bfloat16& h,
                                           __nv_bfloat16& l) {
    h = __float2bfloat16_rn(v);
    l = __float2bfloat16_rn(v - __bfloat162float(h));
}

// ---------------------------------------------------------------------------
// K0: pack weights into mma fragment layout (hi/lo) + zero g_cnt.
// ---------------------------------------------------------------------------
__device__ __forceinline__ float wcat(const float* __restrict__ pre_w,
                                      const float* __restrict__ lin_w,
                                      int o, int k) {
    int seg = k >> 6;
    int ki = k & 63;
    return (seg < 6) ? __ldg(pre_w + (seg * 64 + o) * 64 + ki)
                     : __ldg(lin_w + o * 64 + ki);
}

__global__ void permute_zero_kernel(const float* __restrict__ pre_w,
                                    const float* __restrict__ lin_w, int N) {
    int idx = blockIdx.x * blockDim.x + threadIdx.x;
    if (idx < KSTEPS * 8 * 32) {
        int lane = idx & 31;
        int fg = (idx >> 5) & 7;
        int s = idx >> 8;
        int g = lane >> 2, tg = lane & 3;
        int o = fg * 8 + g;
        int k0 = s * 16 + tg * 2;
        float v0 = wcat(pre_w, lin_w, o, k0);
        float v1 = wcat(pre_w, lin_w, o, k0 + 1);
        float v8 = wcat(pre_w, lin_w, o, k0 + 8);
        float v9 = wcat(pre_w, lin_w, o, k0 + 9);
        __nv_bfloat16 h, l;
        uint32_t bh0, bh1, bl0, bl1;
        bf16_split(v0, h, l); bh0 = bf2us(h);        bl0 = bf2us(l);
        bf16_split(v1, h, l); bh0 |= (uint32_t)bf2us(h) << 16;
                              bl0 |= (uint32_t)bf2us(l) << 16;
        bf16_split(v8, h, l); bh1 = bf2us(h);        bl1 = bf2us(l);
        bf16_split(v9, h, l); bh1 |= (uint32_t)bf2us(h) << 16;
                              bl1 |= (uint32_t)bf2us(l) << 16;
        g_wfh[idx] = (unsigned long long)bh0 | ((unsigned long long)bh1 << 32);
        g_wfl[idx] = (unsigned long long)bl0 | ((unsigned long long)bl1 << 32);
    }
    if (idx < N) g_cnt[idx] = 0;
}

// ---------------------------------------------------------------------------
// K1: histogram + per-edge rank (the only atomic pass)
// ---------------------------------------------------------------------------
__global__ void count_rank_kernel(const int* __restrict__ erow, int E) {
    int e = blockIdx.x * blockDim.x + threadIdx.x;
    if (e < E) g_rank[e] = atomicAdd(&g_cnt[erow[e]], 1);
}

// ---------------------------------------------------------------------------
// K2a/b/c: device-wide exclusive scan
// ---------------------------------------------------------------------------
__global__ void scan_block_kernel(int n) {
    __shared__ int warp_sums[32];
    int i = blockIdx.x * SCAN_BLK + threadIdx.x;
    int v = (i < n) ? g_cnt[i] : 0;
    int lane = threadIdx.x & 31;
    int wid = threadIdx.x >> 5;

    int s = v;
    #pragma unroll
    for (int o = 1; o < 32; o <<= 1) {
        int t = __shfl_up_sync(0xffffffffu, s, o);
        if (lane >= o) s += t;
    }
    if (lane == 31) warp_sums[wid] = s;
    __syncthreads();
    if (wid == 0) {
        int ws = warp_sums[lane];
        #pragma unroll
        for (int o = 1; o < 32; o <<= 1) {
            int t = __shfl_up_sync(0xffffffffu, ws, o);
            if (lane >= o) ws += t;
        }
        warp_sums[lane] = ws;
    }
    __syncthreads();
    int warp_off = (wid == 0) ? 0 : warp_sums[wid - 1];
    if (i < n) g_rowptr[i] = warp_off + s - v;
    if (threadIdx.x == SCAN_BLK - 1) g_bsum[blockIdx.x] = warp_off + s;
}

__global__ void scan_top_kernel(int nb) {
    __shared__ int sh[128];
    int t = threadIdx.x;
    int v = (t < nb) ? g_bsum[t] : 0;
    int lane = t & 31, wid = t >> 5;
    int s = v;
    #pragma unroll
    for (int o = 1; o < 32; o <<= 1) {
        int u = __shfl_up_sync(0xffffffffu, s, o);
        if (lane >= o) s += u;
    }
    if (lane == 31) sh[wid] = s;
    __syncthreads();
    if (t == 0) {
        int acc = 0;
        #pragma unroll
        for (int w = 0; w < 4; ++w) { int x = sh[w]; sh[w] = acc; acc += x; }
    }
    __syncthreads();
    if (t < nb) g_bsum[t] = sh[wid] + s - v;
}

__global__ void scan_add_kernel(int n, int E) {
    int i = blockIdx.x * blockDim.x + threadIdx.x;
    if (i < n) g_rowptr[i] += g_bsum[i >> 10];
    if (i == n) g_rowptr[n] = E;
}

// ---------------------------------------------------------------------------
// K3: atomic-free scatter using precomputed ranks
// ---------------------------------------------------------------------------
__global__ void scatter_kernel(const int* __restrict__ erow,
                               const int* __restrict__ ecol, int E) {
    int e = blockIdx.x * blockDim.x + threadIdx.x;
    if (e < E) {
        int d = erow[e];
        int pos = __ldg(&g_rowptr[d]) + g_rank[e];
        g_csr[pos] = ecol[e];
    }
}

// ---------------------------------------------------------------------------
// K4: fused gather + mma finalize. TM=32, 256 threads, 3 CTAs/SM.
// Single fused k-loop: per kk load Yh/Yl A-frags and Wh/Wl B-frags ONCE,
// issue 3 MMAs (Yh*Wh + Yl*Wh + Yh*Wl) into the same accumulators.
// ---------------------------------------------------------------------------
__device__ __forceinline__ void mma16816(float& c0, float& c1, float& c2,
                                         float& c3, uint32_t a0, uint32_t a1,
                                         uint32_t a2, uint32_t a3,
                                         uint32_t b0, uint32_t b1) {
    asm volatile(
        "mma.sync.aligned.m16n8k16.row.col.f32.bf16.bf16.f32 "
        "{%0,%1,%2,%3},{%4,%5,%6,%7},{%8,%9},{%0,%1,%2,%3};"
        : "+f"(c0), "+f"(c1), "+f"(c2), "+f"(c3)
        : "r"(a0), "r"(a1), "r"(a2), "r"(a3), "r"(b0), "r"(b1));
}

__device__ __forceinline__ unsigned long long pack4bf(
    float v0, float v1, float v2, float v3, bool lo) {
    __nv_bfloat16 h, l;
    uint32_t w0, w1;
    bf16_split(v0, h, l); w0 = lo ? bf2us(l) : bf2us(h);
    bf16_split(v1, h, l); w0 |= (uint32_t)(lo ? bf2us(l) : bf2us(h)) << 16;
    bf16_split(v2, h, l); w1 = lo ? bf2us(l) : bf2us(h);
    bf16_split(v3, h, l); w1 |= (uint32_t)(lo ? bf2us(l) : bf2us(h)) << 16;
    return (unsigned long long)w0 | ((unsigned long long)w1 << 32);
}

__global__ void __launch_bounds__(256, 3)
finalize_fused_kernel(const float* __restrict__ x,
                      const float* __restrict__ bias,
                      const float* __restrict__ avg_ptr,
                      float* __restrict__ out,
                      int N) {
    extern __shared__ __nv_bfloat16 Ybuf[];        // Yh [32][456], Yl [32][456]
    __nv_bfloat16* Yh = Ybuf;
    __nv_bfloat16* Yl = Ybuf + TM * YSTRIDE;
    __shared__ float f1s[TM], f2s[TM];

    const int tid = threadIdx.x;
    const int node0 = blockIdx.x * TM;

    // ---- phase 0: per-node degree factors ----
    if (tid < TM) {
        int n = node0 + tid;
        float f1 = 0.f, f2 = 0.f;
        if (n < N) {
            float avg = __ldg(avg_ptr);
            float degf = (float)(__ldg(&g_rowptr[n + 1]) - __ldg(&g_rowptr[n]));
            float logd = __logf(degf + 1.0f);
            f1 = logd * __frcp_rn(avg);
            f2 = avg * __frcp_rn(logd + EPSV);
        }
        f1s[tid] = f1;
        f2s[tid] = f2;
    }
    __syncthreads();

    // ---- phase 1: gather + stage Y hi/lo (16 lanes/node, 2 subtiles) ----
    {
        const int lane16 = tid & 15;
        const int nsub = tid >> 4;                 // 0..15
        const float4* x4 = reinterpret_cast<const float4*>(x);

        #pragma unroll
        for (int sub = 0; sub < 2; ++sub) {
            int nl = sub * 16 + nsub;
            int n = node0 + nl;
            float4 a = make_float4(0.f, 0.f, 0.f, 0.f);
            float4 b = make_float4(0.f, 0.f, 0.f, 0.f);
            float4 xv = make_float4(0.f, 0.f, 0.f, 0.f);
            if (n < N) {
                int beg = __ldg(&g_rowptr[n]);
                int end = __ldg(&g_rowptr[n + 1]);
                int j = beg;
                for (; j + 1 < end; j += 2) {
                    int s0 = __ldg(&g_csr[j]);
                    int s1 = __ldg(&g_csr[j + 1]);
                    float4 v0 = __ldg(&x4[(size_t)s0 * 16 + lane16]);
                    float4 v1 = __ldg(&x4[(size_t)s1 * 16 + lane16]);
                    a.x += v0.x; a.y += v0.y; a.z += v0.z; a.w += v0.w;
                    b.x += v0.x * v0.x; b.y += v0.y * v0.y;
                    b.z += v0.z * v0.z; b.w += v0.w * v0.w;
                    a.x += v1.x; a.y += v1.y; a.z += v1.z; a.w += v1.w;
                    b.x += v1.x * v1.x; b.y += v1.y * v1.y;
                    b.z += v1.z * v1.z; b.w += v1.w * v1.w;
                }
                if (j < end) {
                    int s0 = __ldg(&g_csr[j]);
                    float4 v0 = __ldg(&x4[(size_t)s0 * 16 + lane16]);
                    a.x += v0.x; a.y += v0.y; a.z += v0.z; a.w += v0.w;
                    b.x += v0.x * v0.x; b.y += v0.y * v0.y;
                    b.z += v0.z * v0.z; b.w += v0.w * v0.w;
                }
                xv = __ldg(&x4[(size_t)n * 16 + lane16]);
            }
            float sx = fmaxf(b.x - a.x * a.x, 0.f) + EPSV;
            float sy = fmaxf(b.y - a.y * a.y, 0.f) + EPSV;
            float sz = fmaxf(b.z - a.z * a.z, 0.f) + EPSV;
            float sw = fmaxf(b.w - a.w * a.w, 0.f) + EPSV;
            float4 sd = make_float4(sx * rsqrtf(sx), sy * rsqrtf(sy),
                                    sz * rsqrtf(sz), sw * rsqrtf(sw));
            float f1 = f1s[nl], f2 = f2s[nl];

            unsigned long long* Yh64 = reinterpret_cast<unsigned long long*>(
                Yh + nl * YSTRIDE) + lane16;
            unsigned long long* Yl64 = reinterpret_cast<unsigned long long*>(
                Yl + nl * YSTRIDE) + lane16;

            float4 segv[7];
            segv[0] = a;
            segv[1] = make_float4(f1 * a.x, f1 * a.y, f1 * a.z, f1 * a.w);
            segv[2] = make_float4(f2 * a.x, f2 * a.y, f2 * a.z, f2 * a.w);
            segv[3] = sd;
            segv[4] = make_float4(f1 * sd.x, f1 * sd.y, f1 * sd.z, f1 * sd.w);
            segv[5] = make_float4(f2 * sd.x, f2 * sd.y, f2 * sd.z, f2 * sd.w);
            segv[6] = xv;
            #pragma unroll
            for (int sg = 0; sg < 7; ++sg) {
                Yh64[sg * 16] = pack4bf(segv[sg].x, segv[sg].y,
                                        segv[sg].z, segv[sg].w, false);
                Yl64[sg * 16] = pack4bf(segv[sg].x, segv[sg].y,
                                        segv[sg].z, segv[sg].w, true);
            }
        }
    }
    __syncthreads();

    // ---- phase 2: fused MMA. warp = 16 nodes x 16 outs, 3 MMAs/frag ----
    const int wid = tid >> 5;
    const int lane = tid & 31;
    const int nh2 = wid & 1;           // node group: 16 nodes
    const int oh = wid >> 1;           // out quarter: oh*16 .. +15
    const int g = lane >> 2;
    const int tg = lane & 3;

    float acc[2][4];
    #pragma unroll
    for (int fi = 0; fi < 2; ++fi)
        #pragma unroll
        for (int q = 0; q < 4; ++q) acc[fi][q] = 0.f;

    const int r0 = (nh2 * 16 + g) * YSTRIDE;

    #pragma unroll 4
    for (int s = 0; s < KSTEPS; ++s) {
        int kk = s * 16 + tg * 2;
        uint32_t ah0 = *(const uint32_t*)(Yh + r0 + kk);
        uint32_t ah1 = *(const uint32_t*)(Yh + r0 + 8 * YSTRIDE + kk);
        uint32_t ah2 = *(const uint32_t*)(Yh + r0 + kk + 8);
        uint32_t ah3 = *(const uint32_t*)(Yh + r0 + 8 * YSTRIDE + kk + 8);
        uint32_t al0 = *(const uint32_t*)(Yl + r0 + kk);
        uint32_t al1 = *(const uint32_t*)(Yl + r0 + 8 * YSTRIDE + kk);
        uint32_t al2 = *(const uint32_t*)(Yl + r0 + kk + 8);
        uint32_t al3 = *(const uint32_t*)(Yl + r0 + 8 * YSTRIDE + kk + 8);
        #pragma unroll
        for (int fi = 0; fi < 2; ++fi) {
            int fg = oh * 2 + fi;
            unsigned long long bh = __ldg(&g_wfh[(s * 8 + fg) * 32 + lane]);
            unsigned long long bl = __ldg(&g_wfl[(s * 8 + fg) * 32 + lane]);
            uint32_t bh0 = (uint32_t)bh, bh1 = (uint32_t)(bh >> 32);
            uint32_t bl0 = (uint32_t)bl, bl1 = (uint32_t)(bl >> 32);
            mma16816(acc[fi][0], acc[fi][1], acc[fi][2], acc[fi][3],
                     ah0, ah1, ah2, ah3, bh0, bh1);     // Yh * Wh
            mma16816(acc[fi][0], acc[fi][1], acc[fi][2], acc[fi][3],
                     al0, al1, al2, al3, bh0, bh1);     // Yl * Wh
            mma16816(acc[fi][0], acc[fi][1], acc[fi][2], acc[fi][3],
                     ah0, ah1, ah2, ah3, bl0, bl1);     // Yh * Wl
        }
    }

    // ---- epilogue ----
    #pragma unroll
    for (int fi = 0; fi < 2; ++fi) {
        int o = oh * 16 + fi * 8 + tg * 2;
        float b0 = __ldg(bias + o);
        float b1 = __ldg(bias + o + 1);
        int n0 = node0 + nh2 * 16 + g;
        int n1 = n0 + 8;
        if (n0 < N) {
            *reinterpret_cast<float2*>(out + (size_t)n0 * D + o) =
                make_float2(acc[fi][0] + b0, acc[fi][1] + b1);
        }
        if (n1 < N) {
            *reinterpret_cast<float2*>(out + (size_t)n1 * D + o) =
                make_float2(acc[fi][2] + b0, acc[fi][3] + b1);
        }
    }
}

// ---------------------------------------------------------------------------
// Launch. Inputs: x, edge_row, edge_col, pre_w, lin_w, bias, avg_deg_log
// ---------------------------------------------------------------------------
extern "C" void kernel_launch(void* const* d_in, const int* in_sizes, int n_in,
                              void* d_out, int out_size) {
    const float* x       = (const float*)d_in[0];
    const int*   erow    = (const int*)d_in[1];
    const int*   ecol    = (const int*)d_in[2];
    const float* pre_w   = (const float*)d_in[3];
    const float* lin_w   = (const float*)d_in[4];
    const float* bias    = (const float*)d_in[5];
    const float* avg_log = (const float*)d_in[6];

    const int N = in_sizes[0] / D;
    const int E = in_sizes[1];
    float* out = (float*)d_out;

    permute_zero_kernel<<<(N + 255) / 256, 256>>>(pre_w, lin_w, N);
    count_rank_kernel<<<(E + 255) / 256, 256>>>(erow, E);
    int nsb = (N + SCAN_BLK - 1) / SCAN_BLK;
    scan_block_kernel<<<nsb, SCAN_BLK>>>(N);
    scan_top_kernel<<<1, 128>>>(nsb);
    scan_add_kernel<<<(N + 256) / 256, 256>>>(N, E);
    scatter_kernel<<<(E + 255) / 256, 256>>>(erow, ecol, E);

    {
        cudaFuncSetAttribute(finalize_fused_kernel,
                             cudaFuncAttributeMaxDynamicSharedMemorySize,
                             FIN_SMEM);
        int blocks = (N + TM - 1) / TM;
        finalize_fused_kernel<<<blocks, 256, FIN_SMEM>>>(
            x, bias, avg_log, out, N);
    }
}